// round 5
// baseline (speedup 1.0000x reference)
#include <cuda_runtime.h>
#include <math.h>

// ---------------- problem dims ----------------
#define TT    10
#define BBs   4
#define CCh   256
#define NP    256          // H*W = 16*16
#define TRR   40           // STEP*RATIO
#define HIDD  1024
#define EPSL  1e-5f

#define BCN   (BBs*CCh*NP)     // 262144
#define BHN   (BBs*HIDD*NP)    // 1048576
#define S_TBCN  (TT*BCN)
#define S_TRBCN (TRR*BBs*CCh*NP)

// ---------------- packed fp32x2 helpers (sm_103a FFMA2 path) ----------------
#define FMA2(d,a,b)  asm("fma.rn.f32x2 %0, %1, %2, %0;" : "+l"(d) : "l"(a), "l"(b))
#define PACK2(d,x)   asm("mov.b64 %0, {%1, %1};" : "=l"(d) : "r"(__float_as_uint(x)))
#define UNPACK2(lo,hi,v) asm("mov.b64 {%0, %1}, %2;" : "=r"(lo), "=r"(hi) : "l"(v))

// ---------------- scratch ----------------
__device__ float g_bufA[S_TRBCN];   // fc1 out (t,b,o,n)
__device__ float g_bufB[S_TRBCN];   // conv1 spikes (u,b,c,n) / fc1 spikes
__device__ float g_y[S_TBCN];       // generic (t,b,c,n) staging
__device__ float g_qs[S_TBCN];
__device__ float g_ks[S_TBCN];
__device__ float g_vs[S_TBCN];
__device__ float g_o[S_TBCN];
__device__ float g_h[S_TBCN];
__device__ float g_ktv[TT*BBs*16*256];
__device__ float g_scale[HIDD];
__device__ float g_shift[HIDD];
__device__ float g_t1s[TRR], g_t1h[TRR];
__device__ float g_t2s[TT],  g_t2h[TT];

// ---------------- BN folding ----------------
__global__ void prep_bn_kernel(const float* __restrict__ bnp, const float* __restrict__ bias,
                               float* __restrict__ scale, float* __restrict__ shift, int cnum)
{
    int i = blockIdx.x * blockDim.x + threadIdx.x;
    if (i >= cnum) return;
    float g  = bnp[i];
    float be = bnp[cnum + i];
    float m  = bnp[2*cnum + i];
    float v  = bnp[3*cnum + i];
    float s  = g / sqrtf(v + EPSL);
    float sh = be - m * s;
    if (bias) sh += bias[i] * s;
    scale[i] = s;
    shift[i] = sh;
}

// ---------------- batched GEMM + BN epilogue, FFMA2 + double-buffered smem ----------------
// Out[batch, o, n] = (sum_k W[o,k] * In[batch,k,n]) * scale[o] + shift[o]
__global__ void gemm_bn_kernel(const float* __restrict__ In, const float* __restrict__ Wm,
                               float* __restrict__ Out, int O, int K,
                               const float* __restrict__ scale, const float* __restrict__ shift)
{
    __shared__ __align__(16) float sA[2][16][64];   // [buf][k][o]
    __shared__ __align__(16) float sB[2][16][64];   // [buf][k][n]
    int batch = blockIdx.z;
    int oBase = blockIdx.y * 64;
    int nBase = blockIdx.x * 64;
    const float* Bp = In + (size_t)batch * K * NP;
    float* Cp = Out + (size_t)batch * O * NP;
    int tid = threadIdx.x;
    int tx = tid & 15, ty = tid >> 4;
    int aoo = tid >> 2, ak4 = (tid & 3) << 2;
    int bkk = tid >> 4, bn4 = (tid & 15) << 2;

    const float* wp = &Wm[(size_t)(oBase + aoo) * K + ak4];
    const float* bp = &Bp[(size_t)bkk * NP + nBase + bn4];

    float4 av = *(const float4*)wp;
    float4 bv = *(const float4*)bp;
    sA[0][ak4 + 0][aoo] = av.x; sA[0][ak4 + 1][aoo] = av.y;
    sA[0][ak4 + 2][aoo] = av.z; sA[0][ak4 + 3][aoo] = av.w;
    *(float4*)&sB[0][bkk][bn4] = bv;
    __syncthreads();

    unsigned long long acc[4][2];
#pragma unroll
    for (int i = 0; i < 4; i++) { acc[i][0] = 0ULL; acc[i][1] = 0ULL; }

    int nk = K >> 4;
    for (int kt = 0; kt < nk; kt++) {
        int cur = kt & 1;
        if (kt + 1 < nk) {
            av = *(const float4*)(wp + (kt + 1) * 16);
            bv = *(const float4*)(bp + (size_t)(kt + 1) * 16 * NP);
        }
#pragma unroll
        for (int kk = 0; kk < 16; kk++) {
            float4 a = *(const float4*)&sA[cur][kk][ty << 2];
            ulonglong2 b = *(const ulonglong2*)&sB[cur][kk][tx << 2];
            unsigned long long p0, p1, p2, p3;
            PACK2(p0, a.x); PACK2(p1, a.y); PACK2(p2, a.z); PACK2(p3, a.w);
            FMA2(acc[0][0], p0, b.x); FMA2(acc[0][1], p0, b.y);
            FMA2(acc[1][0], p1, b.x); FMA2(acc[1][1], p1, b.y);
            FMA2(acc[2][0], p2, b.x); FMA2(acc[2][1], p2, b.y);
            FMA2(acc[3][0], p3, b.x); FMA2(acc[3][1], p3, b.y);
        }
        if (kt + 1 < nk) {
            int nxt = cur ^ 1;
            sA[nxt][ak4 + 0][aoo] = av.x; sA[nxt][ak4 + 1][aoo] = av.y;
            sA[nxt][ak4 + 2][aoo] = av.z; sA[nxt][ak4 + 3][aoo] = av.w;
            *(float4*)&sB[nxt][bkk][bn4] = bv;
        }
        __syncthreads();
    }
#pragma unroll
    for (int i = 0; i < 4; i++) {
        int o = oBase + (ty << 2) + i;
        float sc = scale[o], sh = shift[o];
        unsigned r0, r1, r2, r3;
        UNPACK2(r0, r1, acc[i][0]);
        UNPACK2(r2, r3, acc[i][1]);
        float4 r;
        r.x = __uint_as_float(r0) * sc + sh;
        r.y = __uint_as_float(r1) * sc + sh;
        r.z = __uint_as_float(r2) * sc + sh;
        r.w = __uint_as_float(r3) * sc + sh;
        *(float4*)&Cp[(size_t)o * NP + nBase + (tx << 2)] = r;
    }
}

// ---------------- TIM conv1 + BN + fused LIF1: in (t,b,c,n) -> spikes (u,b,c,n) ----------------
// FFMA2 over u-pairs (weight pairs come naturally from ulonglong2 smem loads).
#define CONV1_SMEM ((10800 + 10*3*18*19) * 4)
__global__ __launch_bounds__(256, 2)
void tim_conv1_kernel(const float* __restrict__ in, const float* __restrict__ wup,
                      const float* __restrict__ sc, const float* __restrict__ sh,
                      float* __restrict__ out)
{
    extern __shared__ float smem[];
    float* sW  = smem;            // [270][40]  (u fastest, 160B rows -> 16B aligned)
    float* sIn = smem + 10800;    // [t*3+dc][18][pitch 19]
    int c = blockIdx.x;
    int b = blockIdx.y;
    int tid = threadIdx.x;

    for (int i = tid; i < 10800; i += 256) {
        int u = i / 270, k = i % 270;
        sW[k * 40 + u] = wup[u * 270 + k];
    }
    for (int i = tid; i < 10 * 3 * 18 * 18; i += 256) {
        int ww = i % 18; int tmp = i / 18;
        int hh = tmp % 18; tmp /= 18;
        int dc = tmp % 3;  int t = tmp / 3;
        int ci = c + dc - 1;
        int hy = hh - 1, wx = ww - 1;
        float v = 0.f;
        if (ci >= 0 && ci < CCh && hy >= 0 && hy < 16 && wx >= 0 && wx < 16)
            v = in[(((size_t)t * BBs + b) * CCh + ci) * NP + hy * 16 + wx];
        sIn[((t * 3 + dc) * 18 + hh) * 19 + ww] = v;
    }
    __syncthreads();

    int h = tid >> 4, w = tid & 15;
    unsigned long long acc[20];
#pragma unroll
    for (int j = 0; j < 20; j++) acc[j] = 0ULL;

#pragma unroll 1
    for (int t = 0; t < 10; t++) {
#pragma unroll
        for (int dc = 0; dc < 3; dc++) {
#pragma unroll
            for (int dh = 0; dh < 3; dh++) {
                const float* rowp = &sIn[((t * 3 + dc) * 18 + h + dh) * 19 + w];
                const ulonglong2* wb = (const ulonglong2*)&sW[((t * 3 + dc) * 3 + dh) * 3 * 40];
#pragma unroll
                for (int dw = 0; dw < 3; dw++) {
                    unsigned long long vp; PACK2(vp, rowp[dw]);
                    const ulonglong2* wq = wb + dw * 10;
#pragma unroll
                    for (int uq = 0; uq < 10; uq++) {
                        ulonglong2 w2 = wq[uq];
                        FMA2(acc[2 * uq + 0], vp, w2.x);
                        FMA2(acc[2 * uq + 1], vp, w2.y);
                    }
                }
            }
        }
    }

    float y[40];
#pragma unroll
    for (int j = 0; j < 20; j++) {
        unsigned lo, hi;
        UNPACK2(lo, hi, acc[j]);
        y[2 * j + 0] = __uint_as_float(lo);
        y[2 * j + 1] = __uint_as_float(hi);
    }
#pragma unroll
    for (int u = 0; u < 40; u++) y[u] = y[u] * sc[u] + sh[u];

    // fused LIF1: scan s over u = 4s + r (matches reference reshape semantics)
#pragma unroll
    for (int r = 0; r < 4; r++) {
        float mem = 0.f;
#pragma unroll
        for (int s = 0; s < 10; s++) {
            int u = 4 * s + r;
            float x = y[u];
            mem = mem + (x - mem) * 0.5f;
            float spk = ((mem - 1.0f) > 0.f) ? 1.f : 0.f;
            out[(((size_t)u * BBs + b) * CCh + c) * NP + tid] = spk;
            if (spk != 0.f) mem = 0.f;
        }
    }
}

// ---------------- TIM conv2 (grouped) + BN + fused LIF2: spikes (u,b,c,n) -> spikes (t,b,c,n) ----
__global__ void tim_conv2_kernel(const float* __restrict__ sp, const float* __restrict__ wdn,
                                 const float* __restrict__ sc, const float* __restrict__ sh,
                                 float* __restrict__ out)
{
    __shared__ float sW[1080];
    __shared__ float sIn[12][18 * 19];   // [r*3+dc][padded 18x18]
    int c = blockIdx.x;
    int b = blockIdx.y;
    int tid = threadIdx.x;
    for (int i = tid; i < 1080; i += 256) sW[i] = wdn[i];

    int h = tid >> 4, w = tid & 15;
    float mem = 0.f;

#pragma unroll 1
    for (int t = 0; t < 10; t++) {
        __syncthreads();
        for (int i = tid; i < 12 * 18 * 18; i += 256) {
            int ww = i % 18; int tmp = i / 18;
            int hh = tmp % 18; int pl = tmp / 18;     // pl = r*3 + dc
            int r = pl / 3, dc = pl % 3;
            int u = 4 * t + r;
            int ci = c + dc - 1;
            int hy = hh - 1, wx = ww - 1;
            float v = 0.f;
            if (ci >= 0 && ci < CCh && hy >= 0 && hy < 16 && wx >= 0 && wx < 16)
                v = sp[(((size_t)u * BBs + b) * CCh + ci) * NP + hy * 16 + wx];
            sIn[pl][hh * 19 + ww] = v;
        }
        __syncthreads();

        float acc = 0.f;
#pragma unroll
        for (int r = 0; r < 4; r++) {
#pragma unroll
            for (int dc = 0; dc < 3; dc++) {
                const float* wr = &sW[(4 * t + r) * 27 + dc * 9];
                const float* pp = &sIn[r * 3 + dc][0];
#pragma unroll
                for (int dh = 0; dh < 3; dh++) {
                    const float* rp = &pp[(h + dh) * 19 + w];
                    acc += rp[0] * wr[dh * 3 + 0];
                    acc += rp[1] * wr[dh * 3 + 1];
                    acc += rp[2] * wr[dh * 3 + 2];
                }
            }
        }
        float yv = acc * sc[t] + sh[t];
        mem = mem + (yv - mem) * 0.5f;
        float spk = ((mem - 1.0f) > 0.f) ? 1.f : 0.f;
        out[(((size_t)t * BBs + b) * CCh + c) * NP + tid] = spk;
        if (spk != 0.f) mem = 0.f;
    }
}

// ---------------- LIF: 10-step scan; spikes out ----------------
__global__ void lif_kernel(const float* __restrict__ in, float* __restrict__ out,
                           int nChains, int stride, float vth)
{
    int i = blockIdx.x * blockDim.x + threadIdx.x;
    if (i >= nChains) return;
    float mem = 0.f;
    int p = i;
#pragma unroll
    for (int s = 0; s < 10; s++, p += stride) {
        float x = in[p];
        mem = mem + (x - mem) * 0.5f;
        float spk = ((mem - vth) > 0.f) ? 1.f : 0.f;
        out[p] = spk;
        if (spk != 0.f) mem = 0.f;
    }
}

__global__ void lif_resid_kernel(const float* __restrict__ in, const float* __restrict__ res,
                                 float* __restrict__ out, int nChains, int stride, float vth)
{
    int i = blockIdx.x * blockDim.x + threadIdx.x;
    if (i >= nChains) return;
    float mem = 0.f;
    int p = i;
#pragma unroll
    for (int s = 0; s < 10; s++, p += stride) {
        float x = in[p];
        mem = mem + (x - mem) * 0.5f;
        float spk = ((mem - vth) > 0.f) ? 1.f : 0.f;
        out[p] = res[p] + spk;
        if (spk != 0.f) mem = 0.f;
    }
}

// ---------------- KtV: per (t,b,head): 16x16 Gram over N ----------------
__global__ void ktv_kernel(const float* __restrict__ ks, const float* __restrict__ vs,
                           float* __restrict__ ktv)
{
    __shared__ float kT[16 * 257];
    __shared__ float vT[16 * 257];
    int tbh = blockIdx.x;
    int hh = tbh & 15;
    int tb = tbh >> 4;
    size_t base = ((size_t)tb * CCh + hh * 16) * NP;
    int tid = threadIdx.x;
    for (int i = tid; i < 16 * 256; i += 256) {
        int r = i >> 8, n = i & 255;
        kT[r * 257 + n] = ks[base + (size_t)r * NP + n];
        vT[r * 257 + n] = vs[base + (size_t)r * NP + n];
    }
    __syncthreads();
    int dd = tid >> 4, de = tid & 15;
    const float* kr = &kT[dd * 257];
    const float* vr = &vT[de * 257];
    float acc = 0.f;
#pragma unroll 8
    for (int n = 0; n < 256; n++) acc += kr[n] * vr[n];
    ktv[(size_t)tbh * 256 + dd * 16 + de] = acc;
}

// ---------------- attn out: o = 0.25 * Q (KtV) ----------------
__global__ void attn_o_kernel(const float* __restrict__ qs, const float* __restrict__ ktv,
                              float* __restrict__ o)
{
    __shared__ float sK[256];
    int tbh = blockIdx.x;
    int hh = tbh & 15;
    int tb = tbh >> 4;
    int tid = threadIdx.x;
    sK[tid] = ktv[(size_t)tbh * 256 + tid];
    __syncthreads();
    size_t base = ((size_t)tb * CCh + hh * 16) * NP + tid;
    float q[16];
#pragma unroll
    for (int d = 0; d < 16; d++) q[d] = qs[base + (size_t)d * NP];
#pragma unroll
    for (int dp = 0; dp < 16; dp++) {
        float acc = 0.f;
#pragma unroll
        for (int d = 0; d < 16; d++) acc += q[d] * sK[d * 16 + dp];
        o[base + (size_t)dp * NP] = acc * 0.25f;
    }
}

// ---------------- orchestration ----------------
extern "C" void kernel_launch(void* const* d_in, const int* in_sizes, int n_in,
                              void* d_out, int out_size)
{
    (void)in_sizes; (void)n_in; (void)out_size;
    const float* x        = (const float*)d_in[0];
    const float* q_w      = (const float*)d_in[1];
    const float* q_bn     = (const float*)d_in[2];
    const float* k_w      = (const float*)d_in[3];
    const float* k_bn     = (const float*)d_in[4];
    const float* v_w      = (const float*)d_in[5];
    const float* v_bn     = (const float*)d_in[6];
    const float* proj_w   = (const float*)d_in[7];
    const float* proj_bn  = (const float*)d_in[8];
    const float* tim_up_w = (const float*)d_in[9];
    const float* tim_bn1  = (const float*)d_in[10];
    const float* tim_dn_w = (const float*)d_in[11];
    const float* tim_bn2  = (const float*)d_in[12];
    const float* fc1_w    = (const float*)d_in[13];
    const float* fc1_b    = (const float*)d_in[14];
    const float* fc1_bn   = (const float*)d_in[15];
    const float* fc2_w    = (const float*)d_in[16];
    const float* fc2_b    = (const float*)d_in[17];
    const float* fc2_bn   = (const float*)d_in[18];
    float* outp = (float*)d_out;

    float *bufA, *bufB, *ybuf, *qs, *ks, *vs, *obuf, *hbuf, *ktv;
    float *scal, *shif, *t1s, *t1h, *t2s, *t2h;
    cudaGetSymbolAddress((void**)&bufA, g_bufA);
    cudaGetSymbolAddress((void**)&bufB, g_bufB);
    cudaGetSymbolAddress((void**)&ybuf, g_y);
    cudaGetSymbolAddress((void**)&qs,   g_qs);
    cudaGetSymbolAddress((void**)&ks,   g_ks);
    cudaGetSymbolAddress((void**)&vs,   g_vs);
    cudaGetSymbolAddress((void**)&obuf, g_o);
    cudaGetSymbolAddress((void**)&hbuf, g_h);
    cudaGetSymbolAddress((void**)&ktv,  g_ktv);
    cudaGetSymbolAddress((void**)&scal, g_scale);
    cudaGetSymbolAddress((void**)&shif, g_shift);
    cudaGetSymbolAddress((void**)&t1s,  g_t1s);
    cudaGetSymbolAddress((void**)&t1h,  g_t1h);
    cudaGetSymbolAddress((void**)&t2s,  g_t2s);
    cudaGetSymbolAddress((void**)&t2h,  g_t2h);

    cudaFuncSetAttribute(tim_conv1_kernel, cudaFuncAttributeMaxDynamicSharedMemorySize, CONV1_SMEM);

    prep_bn_kernel<<<1, 256>>>(tim_bn1, nullptr, t1s, t1h, TRR);
    prep_bn_kernel<<<1, 256>>>(tim_bn2, nullptr, t2s, t2h, TT);

    const float* bw[3]  = {q_w, k_w, v_w};
    const float* bbn[3] = {q_bn, k_bn, v_bn};
    float* bout[3]      = {qs, ks, vs};

    for (int br = 0; br < 3; br++) {
        prep_bn_kernel<<<1, 256>>>(bbn[br], nullptr, scal, shif, CCh);
        gemm_bn_kernel<<<dim3(4, 4, TT*BBs), 256>>>(x, bw[br], ybuf, CCh, CCh, scal, shif);
        // conv1 + BN + LIF1 fused -> spikes in bufB
        tim_conv1_kernel<<<dim3(CCh, BBs), 256, CONV1_SMEM>>>(ybuf, tim_up_w, t1s, t1h, bufB);
        // conv2 + BN + LIF2 fused -> branch spikes
        tim_conv2_kernel<<<dim3(CCh, BBs), 256>>>(bufB, tim_dn_w, t2s, t2h, bout[br]);
    }

    // attention (linear, binary, exact)
    ktv_kernel<<<TT*BBs*16, 256>>>(ks, vs, ktv);
    attn_o_kernel<<<TT*BBs*16, 256>>>(qs, ktv, obuf);
    lif_kernel<<<(BCN + 255)/256, 256>>>(obuf, obuf, BCN, BCN, 0.5f);   // attn_lif vth=0.5

    // projection + BN + lif; residual h = x + spikes
    prep_bn_kernel<<<1, 256>>>(proj_bn, nullptr, scal, shif, CCh);
    gemm_bn_kernel<<<dim3(4, 4, TT*BBs), 256>>>(obuf, proj_w, ybuf, CCh, CCh, scal, shif);
    lif_resid_kernel<<<(BCN + 255)/256, 256>>>(ybuf, x, hbuf, BCN, BCN, 1.0f);

    // MLP
    prep_bn_kernel<<<(HIDD + 255)/256, 256>>>(fc1_bn, fc1_b, scal, shif, HIDD);
    gemm_bn_kernel<<<dim3(4, 16, TT*BBs), 256>>>(hbuf, fc1_w, bufA, HIDD, CCh, scal, shif);
    lif_kernel<<<(BHN + 255)/256, 256>>>(bufA, bufB, BHN, BHN, 1.0f);

    prep_bn_kernel<<<1, 256>>>(fc2_bn, fc2_b, scal, shif, CCh);
    gemm_bn_kernel<<<dim3(4, 4, TT*BBs), 256>>>(bufB, fc2_w, ybuf, CCh, HIDD, scal, shif);
    lif_resid_kernel<<<(BCN + 255)/256, 256>>>(ybuf, hbuf, outp, BCN, BCN, 1.0f);
}

// round 6
// speedup vs baseline: 1.1141x; 1.1141x over previous
#include <cuda_runtime.h>
#include <math.h>

// ---------------- problem dims ----------------
#define TT    10
#define BBs   4
#define CCh   256
#define NP    256          // H*W = 16*16
#define TRR   40           // STEP*RATIO
#define HIDD  1024
#define EPSL  1e-5f

#define BCN   (BBs*CCh*NP)     // 262144 = 2^18
#define BHN   (BBs*HIDD*NP)    // 1048576
#define S_TBCN  (TT*BCN)       // 2,621,440
#define S_TRBCN (TRR*BBs*CCh*NP) // 10,485,760

// packed fp32x2 (used in conv1 only; harmless if lowered to 2xFFMA)
#define FMA2(d,a,b)  asm("fma.rn.f32x2 %0, %1, %2, %0;" : "+l"(d) : "l"(a), "l"(b))
#define PACK2(d,x)   asm("mov.b64 %0, {%1, %1};" : "=l"(d) : "r"(__float_as_uint(x)))
#define UNPACK2(lo,hi,v) asm("mov.b64 {%0, %1}, %2;" : "=r"(lo), "=r"(hi) : "l"(v))

// ---------------- scratch ----------------
__device__ float g_bufA[S_TRBCN];      // qkv gemm out / conv2 out / fc1 out
__device__ float g_bufB[S_TRBCN];      // fc1 spikes
__device__ float g_spk1[3*S_TRBCN];    // conv1 spikes, [br][u][b][c][n]
__device__ float g_spk2[3*S_TBCN];     // branch spikes, [br][t][b][c][n]
__device__ float g_y[S_TBCN];
__device__ float g_o[S_TBCN];
__device__ float g_h[S_TBCN];
__device__ float g_ktv[TT*BBs*16*256];
__device__ float g_wqkv[3*CCh*CCh];
__device__ float g_scale[HIDD];
__device__ float g_shift[HIDD];
__device__ float g_t1s[TRR], g_t1h[TRR];
__device__ float g_t2s[TT],  g_t2h[TT];

// ---------------- weight concat (q,k,v -> stacked O=768) ----------------
__global__ void concat3_kernel(const float* __restrict__ a, const float* __restrict__ b,
                               const float* __restrict__ c, float* __restrict__ dst, int n)
{
    int i = blockIdx.x * blockDim.x + threadIdx.x;
    if (i < n) dst[i] = a[i];
    else if (i < 2*n) dst[i] = b[i - n];
    else if (i < 3*n) dst[i] = c[i - 2*n];
}

// ---------------- BN folding ----------------
__global__ void prep_bn_kernel(const float* __restrict__ bnp, const float* __restrict__ bias,
                               float* __restrict__ scale, float* __restrict__ shift, int cnum)
{
    int i = blockIdx.x * blockDim.x + threadIdx.x;
    if (i >= cnum) return;
    float g  = bnp[i];
    float be = bnp[cnum + i];
    float m  = bnp[2*cnum + i];
    float v  = bnp[3*cnum + i];
    float s  = g / sqrtf(v + EPSL);
    float sh = be - m * s;
    if (bias) sh += bias[i] * s;
    scale[i] = s;
    shift[i] = sh;
}

// ---------------- batched GEMM + BN epilogue (scalar FFMA, double-buffered) --------
// Out[batch, o, n] = (sum_k W[o,k] * In[batch,k,n]) * scale[o] + shift[o]
__global__ void gemm_bn_kernel(const float* __restrict__ In, const float* __restrict__ Wm,
                               float* __restrict__ Out, int O, int K,
                               const float* __restrict__ scale, const float* __restrict__ shift)
{
    __shared__ __align__(16) float sA[2][16][64];   // [buf][k][o]
    __shared__ __align__(16) float sB[2][16][64];   // [buf][k][n]
    int batch = blockIdx.z;
    int oBase = blockIdx.y * 64;
    int nBase = blockIdx.x * 64;
    const float* Bp = In + (size_t)batch * K * NP;
    float* Cp = Out + (size_t)batch * O * NP;
    int tid = threadIdx.x;
    int tx = tid & 15, ty = tid >> 4;
    int aoo = tid >> 2, ak4 = (tid & 3) << 2;
    int bkk = tid >> 4, bn4 = (tid & 15) << 2;

    const float* wp = &Wm[(size_t)(oBase + aoo) * K + ak4];
    const float* bp = &Bp[(size_t)bkk * NP + nBase + bn4];

    float4 av = *(const float4*)wp;
    float4 bv = *(const float4*)bp;
    sA[0][ak4 + 0][aoo] = av.x; sA[0][ak4 + 1][aoo] = av.y;
    sA[0][ak4 + 2][aoo] = av.z; sA[0][ak4 + 3][aoo] = av.w;
    *(float4*)&sB[0][bkk][bn4] = bv;
    __syncthreads();

    float acc[4][4];
#pragma unroll
    for (int i = 0; i < 4; i++)
#pragma unroll
        for (int j = 0; j < 4; j++) acc[i][j] = 0.f;

    int nk = K >> 4;
    for (int kt = 0; kt < nk; kt++) {
        int cur = kt & 1;
        if (kt + 1 < nk) {
            av = *(const float4*)(wp + (kt + 1) * 16);
            bv = *(const float4*)(bp + (size_t)(kt + 1) * 16 * NP);
        }
#pragma unroll
        for (int kk = 0; kk < 16; kk++) {
            float4 a = *(const float4*)&sA[cur][kk][ty << 2];
            float4 b = *(const float4*)&sB[cur][kk][tx << 2];
            acc[0][0] += a.x * b.x; acc[0][1] += a.x * b.y; acc[0][2] += a.x * b.z; acc[0][3] += a.x * b.w;
            acc[1][0] += a.y * b.x; acc[1][1] += a.y * b.y; acc[1][2] += a.y * b.z; acc[1][3] += a.y * b.w;
            acc[2][0] += a.z * b.x; acc[2][1] += a.z * b.y; acc[2][2] += a.z * b.z; acc[2][3] += a.z * b.w;
            acc[3][0] += a.w * b.x; acc[3][1] += a.w * b.y; acc[3][2] += a.w * b.z; acc[3][3] += a.w * b.w;
        }
        if (kt + 1 < nk) {
            int nxt = cur ^ 1;
            sA[nxt][ak4 + 0][aoo] = av.x; sA[nxt][ak4 + 1][aoo] = av.y;
            sA[nxt][ak4 + 2][aoo] = av.z; sA[nxt][ak4 + 3][aoo] = av.w;
            *(float4*)&sB[nxt][bkk][bn4] = bv;
        }
        __syncthreads();
    }
#pragma unroll
    for (int i = 0; i < 4; i++) {
        int o = oBase + (ty << 2) + i;
        float sc = scale[o], sh = shift[o];
        float4 r;
        r.x = acc[i][0] * sc + sh; r.y = acc[i][1] * sc + sh;
        r.z = acc[i][2] * sc + sh; r.w = acc[i][3] * sc + sh;
        *(float4*)&Cp[(size_t)o * NP + nBase + (tx << 2)] = r;
    }
}

// ---------------- TIM conv1 + BN + fused LIF1, t-staged, all branches ----------------
// in : stacked qkv gemm out, index ((t*B + b)*768 + br*256 + ci)*256 + n
// out: spikes, index ((br*40 + u)*B + b)*C*N + c*N + n
__global__ __launch_bounds__(256)
void tim_conv1_kernel(const float* __restrict__ in, const float* __restrict__ wup,
                      const float* __restrict__ sc, const float* __restrict__ sh,
                      float* __restrict__ out)
{
    __shared__ __align__(16) float sW[2][1080];       // [tap(27)][u(40)]
    __shared__ float sIn[2][3][18*19];                // [dc][18 rows x pitch 19]
    int c  = blockIdx.x;
    int b  = blockIdx.y;
    int br = blockIdx.z;
    int tid = threadIdx.x;
    const float* inb = in + ((size_t)b * 768 + br * 256) * NP;   // + t*(B*768*NP) + ci*NP

    // ---- prologue: stage t=0 into buffer 0 ----
    {
        float ip[4], wpre[5];
#pragma unroll
        for (int j = 0; j < 4; j++) {
            int i = tid + j * 256;
            float v = 0.f;
            if (i < 972) {
                int dc = i / 324, rem = i % 324;
                int hh = rem / 18, ww = rem % 18;
                int ci = c + dc - 1;
                int hy = hh - 1, wx = ww - 1;
                if (ci >= 0 && ci < CCh && hy >= 0 && hy < 16 && wx >= 0 && wx < 16)
                    v = inb[(size_t)ci * NP + hy * 16 + wx];
            }
            ip[j] = v;
        }
#pragma unroll
        for (int j = 0; j < 5; j++) {
            int i = tid + j * 256;
            float v = 0.f;
            if (i < 1080) {
                int u = i % 40, tap = i / 40;
                v = wup[u * 270 + tap];          // t=0
            }
            wpre[j] = v;
        }
#pragma unroll
        for (int j = 0; j < 4; j++) {
            int i = tid + j * 256;
            if (i < 972) { int dc = i / 324, rem = i % 324; sIn[0][dc][(rem/18)*19 + (rem%18)] = ip[j]; }
        }
#pragma unroll
        for (int j = 0; j < 5; j++) {
            int i = tid + j * 256;
            if (i < 1080) sW[0][i] = wpre[j];
        }
    }
    __syncthreads();

    int h = tid >> 4, w = tid & 15;
    unsigned long long acc[20];
#pragma unroll
    for (int j = 0; j < 20; j++) acc[j] = 0ULL;

#pragma unroll 1
    for (int t = 0; t < 10; t++) {
        int cur = t & 1;
        float ip[4], wpre[5];
        if (t < 9) {
            const float* inb2 = inb + (size_t)(t + 1) * (BBs * 768 * NP);
#pragma unroll
            for (int j = 0; j < 4; j++) {
                int i = tid + j * 256;
                float v = 0.f;
                if (i < 972) {
                    int dc = i / 324, rem = i % 324;
                    int hh = rem / 18, ww = rem % 18;
                    int ci = c + dc - 1;
                    int hy = hh - 1, wx = ww - 1;
                    if (ci >= 0 && ci < CCh && hy >= 0 && hy < 16 && wx >= 0 && wx < 16)
                        v = inb2[(size_t)ci * NP + hy * 16 + wx];
                }
                ip[j] = v;
            }
#pragma unroll
            for (int j = 0; j < 5; j++) {
                int i = tid + j * 256;
                float v = 0.f;
                if (i < 1080) {
                    int u = i % 40, tap = i / 40;
                    v = wup[u * 270 + (t + 1) * 27 + tap];
                }
                wpre[j] = v;
            }
        }

        // ---- compute t from buffer cur ----
#pragma unroll
        for (int dc = 0; dc < 3; dc++) {
#pragma unroll
            for (int dh = 0; dh < 3; dh++) {
                const float* rowp = &sIn[cur][dc][(h + dh) * 19 + w];
#pragma unroll
                for (int dw = 0; dw < 3; dw++) {
                    unsigned long long vp; PACK2(vp, rowp[dw]);
                    const ulonglong2* wq = (const ulonglong2*)&sW[cur][((dc * 3 + dh) * 3 + dw) * 40];
#pragma unroll
                    for (int j = 0; j < 10; j++) {
                        ulonglong2 w2 = wq[j];
                        FMA2(acc[2 * j + 0], vp, w2.x);
                        FMA2(acc[2 * j + 1], vp, w2.y);
                    }
                }
            }
        }

        if (t < 9) {
            int nxt = cur ^ 1;
#pragma unroll
            for (int j = 0; j < 4; j++) {
                int i = tid + j * 256;
                if (i < 972) { int dc = i / 324, rem = i % 324; sIn[nxt][dc][(rem/18)*19 + (rem%18)] = ip[j]; }
            }
#pragma unroll
            for (int j = 0; j < 5; j++) {
                int i = tid + j * 256;
                if (i < 1080) sW[nxt][i] = wpre[j];
            }
        }
        __syncthreads();
    }

    // ---- BN + fused LIF1 epilogue ----
    float y[40];
#pragma unroll
    for (int j = 0; j < 20; j++) {
        unsigned lo, hi;
        UNPACK2(lo, hi, acc[j]);
        y[2 * j + 0] = __uint_as_float(lo);
        y[2 * j + 1] = __uint_as_float(hi);
    }
#pragma unroll
    for (int u = 0; u < 40; u++) y[u] = y[u] * sc[u] + sh[u];

    size_t ob = ((size_t)(br * 40) * BBs + b) * CCh * NP + (size_t)c * NP + tid;
#pragma unroll
    for (int r = 0; r < 4; r++) {
        float mem = 0.f;
#pragma unroll
        for (int s = 0; s < 10; s++) {
            int u = 4 * s + r;
            float xv = y[u];
            mem = mem + (xv - mem) * 0.5f;
            float spk = ((mem - 1.0f) > 0.f) ? 1.f : 0.f;
            out[ob + (size_t)u * (BBs * CCh * NP)] = spk;
            if (spk != 0.f) mem = 0.f;
        }
    }
}

// ---------------- TIM conv2 (grouped) + BN, smem-staged, all branches ----------------
// sp : spikes [br][u][b][c][n];  out: [br][t][b][c][n] (pre-LIF values)
__global__ void tim_conv2_kernel(const float* __restrict__ sp, const float* __restrict__ wdn,
                                 const float* __restrict__ sc, const float* __restrict__ sh,
                                 float* __restrict__ out)
{
    __shared__ float sW[108];
    __shared__ float sIn[12][18 * 19];     // [r*3+dc][padded]
    int c  = blockIdx.x;
    int t  = blockIdx.y;
    int z  = blockIdx.z;
    int b  = z & 3;
    int br = z >> 2;
    int tid = threadIdx.x;

    if (tid < 108) sW[tid] = wdn[t * 108 + tid];
    for (int i = tid; i < 12 * 324; i += 256) {
        int pl = i / 324, rem = i % 324;
        int hh = rem / 18, ww = rem % 18;
        int r = pl / 3, dc = pl % 3;
        int u = t * 4 + r;
        int ci = c + dc - 1;
        int hy = hh - 1, wx = ww - 1;
        float v = 0.f;
        if (ci >= 0 && ci < CCh && hy >= 0 && hy < 16 && wx >= 0 && wx < 16)
            v = sp[(((size_t)(br * 40 + u) * BBs + b) * CCh + ci) * NP + hy * 16 + wx];
        sIn[pl][hh * 19 + ww] = v;
    }
    __syncthreads();

    int h = tid >> 4, w = tid & 15;
    float acc = 0.f;
#pragma unroll
    for (int r = 0; r < 4; r++) {
#pragma unroll
        for (int dc = 0; dc < 3; dc++) {
            const float* wr = &sW[r * 27 + dc * 9];
            const float* pp = &sIn[r * 3 + dc][0];
#pragma unroll
            for (int dh = 0; dh < 3; dh++) {
                const float* rp = &pp[(h + dh) * 19 + w];
                acc += rp[0] * wr[dh * 3 + 0];
                acc += rp[1] * wr[dh * 3 + 1];
                acc += rp[2] * wr[dh * 3 + 2];
            }
        }
    }
    out[(size_t)br * S_TBCN + (((size_t)t * BBs + b) * CCh + c) * NP + tid] = acc * sc[t] + sh[t];
}

// ---------------- LIF variants ----------------
__global__ void lif_kernel(const float* __restrict__ in, float* __restrict__ out,
                           int nChains, int stride, float vth)
{
    int i = blockIdx.x * blockDim.x + threadIdx.x;
    if (i >= nChains) return;
    float mem = 0.f;
    int p = i;
#pragma unroll
    for (int s = 0; s < 10; s++, p += stride) {
        float x = in[p];
        mem = mem + (x - mem) * 0.5f;
        float spk = ((mem - vth) > 0.f) ? 1.f : 0.f;
        out[p] = spk;
        if (spk != 0.f) mem = 0.f;
    }
}

// merged 3-branch lif: in/out laid out [br][t][b][c][n]
__global__ void lif3_kernel(const float* __restrict__ in, float* __restrict__ out, float vth)
{
    int i = blockIdx.x * blockDim.x + threadIdx.x;
    if (i >= 3 * BCN) return;
    int br = i >> 18;
    int j  = i & (BCN - 1);
    size_t p = (size_t)br * S_TBCN + j;
    float mem = 0.f;
#pragma unroll
    for (int s = 0; s < 10; s++, p += BCN) {
        float x = in[p];
        mem = mem + (x - mem) * 0.5f;
        float spk = ((mem - vth) > 0.f) ? 1.f : 0.f;
        out[p] = spk;
        if (spk != 0.f) mem = 0.f;
    }
}

__global__ void lif_resid_kernel(const float* __restrict__ in, const float* __restrict__ res,
                                 float* __restrict__ out, int nChains, int stride, float vth)
{
    int i = blockIdx.x * blockDim.x + threadIdx.x;
    if (i >= nChains) return;
    float mem = 0.f;
    int p = i;
#pragma unroll
    for (int s = 0; s < 10; s++, p += stride) {
        float x = in[p];
        mem = mem + (x - mem) * 0.5f;
        float spk = ((mem - vth) > 0.f) ? 1.f : 0.f;
        out[p] = res[p] + spk;
        if (spk != 0.f) mem = 0.f;
    }
}

// ---------------- KtV: per (t,b,head): 16x16 Gram over N ----------------
__global__ void ktv_kernel(const float* __restrict__ ks, const float* __restrict__ vs,
                           float* __restrict__ ktv)
{
    __shared__ float kT[16 * 257];
    __shared__ float vT[16 * 257];
    int tbh = blockIdx.x;
    int hh = tbh & 15;
    int tb = tbh >> 4;
    size_t base = ((size_t)tb * CCh + hh * 16) * NP;
    int tid = threadIdx.x;
    for (int i = tid; i < 16 * 256; i += 256) {
        int r = i >> 8, n = i & 255;
        kT[r * 257 + n] = ks[base + (size_t)r * NP + n];
        vT[r * 257 + n] = vs[base + (size_t)r * NP + n];
    }
    __syncthreads();
    int dd = tid >> 4, de = tid & 15;
    const float* kr = &kT[dd * 257];
    const float* vr = &vT[de * 257];
    float acc = 0.f;
#pragma unroll 8
    for (int n = 0; n < 256; n++) acc += kr[n] * vr[n];
    ktv[(size_t)tbh * 256 + dd * 16 + de] = acc;
}

// ---------------- attn out: o = 0.25 * Q (KtV) ----------------
__global__ void attn_o_kernel(const float* __restrict__ qs, const float* __restrict__ ktv,
                              float* __restrict__ o)
{
    __shared__ float sK[256];
    int tbh = blockIdx.x;
    int hh = tbh & 15;
    int tb = tbh >> 4;
    int tid = threadIdx.x;
    sK[tid] = ktv[(size_t)tbh * 256 + tid];
    __syncthreads();
    size_t base = ((size_t)tb * CCh + hh * 16) * NP + tid;
    float q[16];
#pragma unroll
    for (int d = 0; d < 16; d++) q[d] = qs[base + (size_t)d * NP];
#pragma unroll
    for (int dp = 0; dp < 16; dp++) {
        float acc = 0.f;
#pragma unroll
        for (int d = 0; d < 16; d++) acc += q[d] * sK[d * 16 + dp];
        o[base + (size_t)dp * NP] = acc * 0.25f;
    }
}

// ---------------- orchestration ----------------
extern "C" void kernel_launch(void* const* d_in, const int* in_sizes, int n_in,
                              void* d_out, int out_size)
{
    (void)in_sizes; (void)n_in; (void)out_size;
    const float* x        = (const float*)d_in[0];
    const float* q_w      = (const float*)d_in[1];
    const float* q_bn     = (const float*)d_in[2];
    const float* k_w      = (const float*)d_in[3];
    const float* k_bn     = (const float*)d_in[4];
    const float* v_w      = (const float*)d_in[5];
    const float* v_bn     = (const float*)d_in[6];
    const float* proj_w   = (const float*)d_in[7];
    const float* proj_bn  = (const float*)d_in[8];
    const float* tim_up_w = (const float*)d_in[9];
    const float* tim_bn1  = (const float*)d_in[10];
    const float* tim_dn_w = (const float*)d_in[11];
    const float* tim_bn2  = (const float*)d_in[12];
    const float* fc1_w    = (const float*)d_in[13];
    const float* fc1_b    = (const float*)d_in[14];
    const float* fc1_bn   = (const float*)d_in[15];
    const float* fc2_w    = (const float*)d_in[16];
    const float* fc2_b    = (const float*)d_in[17];
    const float* fc2_bn   = (const float*)d_in[18];
    float* outp = (float*)d_out;

    float *bufA, *bufB, *spk1, *spk2, *ybuf, *obuf, *hbuf, *ktvb, *wqkv;
    float *scal, *shif, *t1s, *t1h, *t2s, *t2h;
    cudaGetSymbolAddress((void**)&bufA, g_bufA);
    cudaGetSymbolAddress((void**)&bufB, g_bufB);
    cudaGetSymbolAddress((void**)&spk1, g_spk1);
    cudaGetSymbolAddress((void**)&spk2, g_spk2);
    cudaGetSymbolAddress((void**)&ybuf, g_y);
    cudaGetSymbolAddress((void**)&obuf, g_o);
    cudaGetSymbolAddress((void**)&hbuf, g_h);
    cudaGetSymbolAddress((void**)&ktvb, g_ktv);
    cudaGetSymbolAddress((void**)&wqkv, g_wqkv);
    cudaGetSymbolAddress((void**)&scal, g_scale);
    cudaGetSymbolAddress((void**)&shif, g_shift);
    cudaGetSymbolAddress((void**)&t1s,  g_t1s);
    cudaGetSymbolAddress((void**)&t1h,  g_t1h);
    cudaGetSymbolAddress((void**)&t2s,  g_t2s);
    cudaGetSymbolAddress((void**)&t2h,  g_t2h);

    // weight concat + BN folds
    concat3_kernel<<<768, 256>>>(q_w, k_w, v_w, wqkv, CCh * CCh);
    prep_bn_kernel<<<1, 256>>>(q_bn, nullptr, scal,        shif,        CCh);
    prep_bn_kernel<<<1, 256>>>(k_bn, nullptr, scal + 256,  shif + 256,  CCh);
    prep_bn_kernel<<<1, 256>>>(v_bn, nullptr, scal + 512,  shif + 512,  CCh);
    prep_bn_kernel<<<1, 256>>>(tim_bn1, nullptr, t1s, t1h, TRR);
    prep_bn_kernel<<<1, 256>>>(tim_bn2, nullptr, t2s, t2h, TT);

    // merged q/k/v GEMM: Out (tb, 768, n)
    gemm_bn_kernel<<<dim3(4, 12, TT*BBs), 256>>>(x, wqkv, bufA, 768, CCh, scal, shif);

    // TIM: conv1 + BN + LIF1 (all branches), conv2 + BN, LIF2
    tim_conv1_kernel<<<dim3(CCh, BBs, 3), 256>>>(bufA, tim_up_w, t1s, t1h, spk1);
    tim_conv2_kernel<<<dim3(CCh, TT, BBs*3), 256>>>(spk1, tim_dn_w, t2s, t2h, bufA);
    lif3_kernel<<<(3*BCN + 255)/256, 256>>>(bufA, spk2, 1.0f);

    // attention (linear, binary, exact): q=br0, k=br1, v=br2
    ktv_kernel<<<TT*BBs*16, 256>>>(spk2 + S_TBCN, spk2 + 2*S_TBCN, ktvb);
    attn_o_kernel<<<TT*BBs*16, 256>>>(spk2, ktvb, obuf);
    lif_kernel<<<(BCN + 255)/256, 256>>>(obuf, obuf, BCN, BCN, 0.5f);

    // projection + BN + lif; residual h = x + spikes
    prep_bn_kernel<<<1, 256>>>(proj_bn, nullptr, scal, shif, CCh);
    gemm_bn_kernel<<<dim3(4, 4, TT*BBs), 256>>>(obuf, proj_w, ybuf, CCh, CCh, scal, shif);
    lif_resid_kernel<<<(BCN + 255)/256, 256>>>(ybuf, x, hbuf, BCN, BCN, 1.0f);

    // MLP
    prep_bn_kernel<<<(HIDD + 255)/256, 256>>>(fc1_bn, fc1_b, scal, shif, HIDD);
    gemm_bn_kernel<<<dim3(4, 16, TT*BBs), 256>>>(hbuf, fc1_w, bufA, HIDD, CCh, scal, shif);
    lif_kernel<<<(BHN + 255)/256, 256>>>(bufA, bufB, BHN, BHN, 1.0f);

    prep_bn_kernel<<<1, 256>>>(fc2_bn, fc2_b, scal, shif, CCh);
    gemm_bn_kernel<<<dim3(4, 4, TT*BBs), 256>>>(bufB, fc2_w, ybuf, CCh, HIDD, scal, shif);
    lif_resid_kernel<<<(BCN + 255)/256, 256>>>(ybuf, hbuf, outp, BCN, BCN, 1.0f);
}